// round 13
// baseline (speedup 1.0000x reference)
#include <cuda_runtime.h>
#include <cuda_bf16.h>
#include <cstdint>

#define NFIELD 39
#define VOCAB  200000
#define BATCH  16384
#define ROWSPB 128
#define THREADS 512
#define NCHUNK 10          // 10 chunks x 4 fields (kstep16) = 640 padded k

// B fragments, chunk-major: [chunk10][hl2][s4][tp4][lane32][4 u32] = 160KB
__device__ __align__(16) uint32_t BfragG[10 * 2 * 4 * 4 * 32 * 4];

__global__ void prep_kernel(const float* __restrict__ W1, const float* __restrict__ Wi) {
    int i = blockIdx.x * blockDim.x + threadIdx.x;
    if (i >= 10 * 2 * 4 * 4 * 32 * 4) return;
    int reg = i & 3;
    int l   = (i >> 2) & 31;
    int tp  = (i >> 7) & 3;
    int s   = (i >> 9) & 3;
    int hl  = (i >> 11) & 1;
    int c   = i >> 12;
    int gs = c * 4 + s;
    int t  = tp * 2 + (reg >> 1);
    int n  = t * 8 + (l >> 2);
    int k0 = gs * 16 + (l & 3) * 2 + (reg & 1) * 8;
    float v0 = 0.f, v1 = 0.f;
    if (k0 < 624)     v0 = (n < 32) ? W1[n * 624 + k0]     : Wi[(n - 32) * 624 + k0];
    if (k0 + 1 < 624) v1 = (n < 32) ? W1[n * 624 + k0 + 1] : Wi[(n - 32) * 624 + k0 + 1];
    float h0 = __bfloat162float(__float2bfloat16(v0));
    float h1 = __bfloat162float(__float2bfloat16(v1));
    uint32_t w;
    if (hl == 0) {
        asm("cvt.rn.bf16x2.f32 %0, %1, %2;" : "=r"(w) : "f"(h1), "f"(h0));
    } else {
        float r0 = v0 - h0, r1 = v1 - h1;
        asm("cvt.rn.bf16x2.f32 %0, %1, %2;" : "=r"(w) : "f"(r1), "f"(r0));
    }
    BfragG[i] = w;
}

__device__ __forceinline__ uint32_t packbf(float lo_elem, float hi_elem) {
    uint32_t r;
    asm("cvt.rn.bf16x2.f32 %0, %1, %2;" : "=r"(r) : "f"(hi_elem), "f"(lo_elem));
    return r;
}
__device__ __forceinline__ void mma16816(float* d, uint32_t a0, uint32_t a1, uint32_t a2, uint32_t a3,
                                         uint32_t b0, uint32_t b1) {
    asm volatile("mma.sync.aligned.m16n8k16.row.col.f32.bf16.bf16.f32 "
                 "{%0,%1,%2,%3}, {%4,%5,%6,%7}, {%8,%9}, {%0,%1,%2,%3};"
                 : "+f"(d[0]), "+f"(d[1]), "+f"(d[2]), "+f"(d[3])
                 : "r"(a0), "r"(a1), "r"(a2), "r"(a3), "r"(b0), "r"(b1));
}
__device__ __forceinline__ void ldsm4(uint32_t& r0, uint32_t& r1, uint32_t& r2, uint32_t& r3,
                                      uint32_t addr) {
    asm volatile("ldmatrix.sync.aligned.m8n8.x4.shared.b16 {%0,%1,%2,%3}, [%4];"
                 : "=r"(r0), "=r"(r1), "=r"(r2), "=r"(r3) : "r"(addr));
}

// smem (64KB): per-warp A: [warp16][buf2][si2][hl2][512B] = 16 x 4KB
#define SMEM_BYTES 65536
// epilogue aliases:
#define EXP_FO 0        // 128 x 33 floats
#define EXP_S  16896
#define EXP_M  33792    // MLP weights (2145 floats)
#define EXP_H  42384

__global__ __launch_bounds__(THREADS, 1)
void pnn_kernel(const int*   __restrict__ Xi,
                const float* __restrict__ Xv,
                const float* __restrict__ tables,
                const float* __restrict__ lin1_w,
                const float* __restrict__ lin1_b,
                const float* __restrict__ lin2_w,
                const float* __restrict__ lin2_b,
                const float* __restrict__ last_w,
                const float* __restrict__ last_b,
                float*       __restrict__ out) {
    extern __shared__ unsigned char smem[];
    const uint32_t sbase = (uint32_t)__cvta_generic_to_shared(smem);

    const int tid = threadIdx.x;
    const int wid = tid >> 5;
    const int l   = tid & 31;
    const int b0  = blockIdx.x * ROWSPB;

    // warp = (slab, k-half): rows [slab*16, +16), ksteps {2kh, 2kh+1} per chunk
    const int slab = wid >> 1;
    const int kh   = wid & 1;
    const uint32_t awarp = (uint32_t)(wid * 4096);

    // warp-private gather: 4 items/lane/chunk; item it: jh=it&1, h=it>>1
    const int lrow = l >> 2;         // 0..7
    const int q    = l & 3;          // 16B segment

    int    nidx[2][4];
    float  nxv[2][4];
    float4 tdat[4];

    float acc[8][4];                 // all 8 ntiles, half K
    #pragma unroll
    for (int t = 0; t < 8; ++t)
        #pragma unroll
        for (int r = 0; r < 4; ++r) acc[t][r] = 0.f;

    const uint4* __restrict__ Bp = (const uint4*)BfragG;

    auto load_idx = [&](int c) {
        const int slot = c & 1;
        #pragma unroll
        for (int it = 0; it < 4; ++it) {
            int rl = (it >> 1) * 8 + lrow;
            int f  = c * 4 + 2 * kh + (it & 1);
            int row = b0 + slab * 16 + rl;
            if (f < NFIELD) {
                nidx[slot][it] = Xi[(size_t)row * NFIELD + f];
                nxv[slot][it]  = Xv[(size_t)row * NFIELD + f];
            } else {
                nidx[slot][it] = 0;
                nxv[slot][it]  = 0.f;
            }
        }
    };
    auto table_ldg = [&](int c) {
        const int slot = c & 1;
        #pragma unroll
        for (int it = 0; it < 4; ++it) {
            int f = c * 4 + 2 * kh + (it & 1);
            if (f < NFIELD)   // .cg keeps gather stream out of L1 so B stays resident
                tdat[it] = __ldcg(((const float4*)tables) + ((long)f * VOCAB + nidx[slot][it]) * 4 + q);
            else
                tdat[it] = make_float4(0.f, 0.f, 0.f, 0.f);
        }
    };
    auto cv_store = [&](int c) {
        const int slot = c & 1;
        const uint32_t bufo = awarp + (uint32_t)((c & 1) * 2048);
        #pragma unroll
        for (int it = 0; it < 4; ++it) {
            int rl = (it >> 1) * 8 + lrow;
            int si = it & 1;
            float xv = nxv[slot][it];
            float4 t4 = tdat[it];
            float v0 = t4.x * xv, v1 = t4.y * xv, v2 = t4.z * xv, v3 = t4.w * xv;
            float r0 = v0 - __bfloat162float(__float2bfloat16(v0));
            float r1 = v1 - __bfloat162float(__float2bfloat16(v1));
            float r2 = v2 - __bfloat162float(__float2bfloat16(v2));
            float r3 = v3 - __bfloat162float(__float2bfloat16(v3));
            uint32_t inoff = (uint32_t)((q >> 1) * 256 + rl * 16 + (q & 1) * 8);
            unsigned char* bh = smem + bufo + si * 1024 + 0   + inoff;
            unsigned char* bl = smem + bufo + si * 1024 + 512 + inoff;
            *(uint2*)bh = make_uint2(packbf(v0, v1), packbf(v2, v3));
            *(uint2*)bl = make_uint2(packbf(r0, r1), packbf(r2, r3));
        }
    };
    auto do_mma = [&](int c) {
        const uint32_t abase = sbase + awarp + (uint32_t)((c & 1) * 2048);
        const uint32_t laddr = (uint32_t)((l & 15) * 16 + (l >> 4) * 256);
        #pragma unroll
        for (int si = 0; si < 2; ++si) {
            const int s = kh * 2 + si;
            const uint4* bb = Bp + c * 1024 + s * 128 + l;
            uint4 Bh0 = bb[0 * 512 + 0 * 32];
            uint4 Bh1 = bb[0 * 512 + 1 * 32];
            uint4 Bh2 = bb[0 * 512 + 2 * 32];
            uint4 Bh3 = bb[0 * 512 + 3 * 32];
            uint4 Bl0 = bb[1 * 512 + 0 * 32];
            uint4 Bl1 = bb[1 * 512 + 1 * 32];
            uint4 Bl2 = bb[1 * 512 + 2 * 32];
            uint4 Bl3 = bb[1 * 512 + 3 * 32];
            uint32_t ah0, ah1, ah2, ah3, al0, al1, al2, al3;
            ldsm4(ah0, ah1, ah2, ah3, abase + si * 1024 + 0   + laddr);
            ldsm4(al0, al1, al2, al3, abase + si * 1024 + 512 + laddr);
            mma16816(acc[0], ah0, ah1, ah2, ah3, Bh0.x, Bh0.y);
            mma16816(acc[1], ah0, ah1, ah2, ah3, Bh0.z, Bh0.w);
            mma16816(acc[2], ah0, ah1, ah2, ah3, Bh1.x, Bh1.y);
            mma16816(acc[3], ah0, ah1, ah2, ah3, Bh1.z, Bh1.w);
            mma16816(acc[4], ah0, ah1, ah2, ah3, Bh2.x, Bh2.y);
            mma16816(acc[5], ah0, ah1, ah2, ah3, Bh2.z, Bh2.w);
            mma16816(acc[6], ah0, ah1, ah2, ah3, Bh3.x, Bh3.y);
            mma16816(acc[7], ah0, ah1, ah2, ah3, Bh3.z, Bh3.w);
            mma16816(acc[0], ah0, ah1, ah2, ah3, Bl0.x, Bl0.y);
            mma16816(acc[1], ah0, ah1, ah2, ah3, Bl0.z, Bl0.w);
            mma16816(acc[2], ah0, ah1, ah2, ah3, Bl1.x, Bl1.y);
            mma16816(acc[3], ah0, ah1, ah2, ah3, Bl1.z, Bl1.w);
            mma16816(acc[4], ah0, ah1, ah2, ah3, Bl2.x, Bl2.y);
            mma16816(acc[5], ah0, ah1, ah2, ah3, Bl2.z, Bl2.w);
            mma16816(acc[6], ah0, ah1, ah2, ah3, Bl3.x, Bl3.y);
            mma16816(acc[7], ah0, ah1, ah2, ah3, Bl3.z, Bl3.w);
            mma16816(acc[0], al0, al1, al2, al3, Bh0.x, Bh0.y);
            mma16816(acc[1], al0, al1, al2, al3, Bh0.z, Bh0.w);
            mma16816(acc[2], al0, al1, al2, al3, Bh1.x, Bh1.y);
            mma16816(acc[3], al0, al1, al2, al3, Bh1.z, Bh1.w);
            mma16816(acc[4], al0, al1, al2, al3, Bh2.x, Bh2.y);
            mma16816(acc[5], al0, al1, al2, al3, Bh2.z, Bh2.w);
            mma16816(acc[6], al0, al1, al2, al3, Bh3.x, Bh3.y);
            mma16816(acc[7], al0, al1, al2, al3, Bh3.z, Bh3.w);
        }
    };

    // ---- prologue (warp-private; one exposed gather) ----
    load_idx(0);
    load_idx(1);
    table_ldg(0);
    cv_store(0);
    __syncwarp();

    // ---- main loop: NO inter-warp sync; 16 free-running warps ----
    #pragma unroll 1
    for (int c = 0; c < NCHUNK; ++c) {
        if (c + 2 < NCHUNK) load_idx(c + 2);
        if (c + 1 < NCHUNK) table_ldg(c + 1);
        do_mma(c);
        if (c + 1 < NCHUNK) cv_store(c + 1);
        __syncwarp();
    }
    __syncthreads();

    // ---- epilogue: sum k-halves, combine, MLP ----
    float* sFO = (float*)(smem + EXP_FO);
    float* sS  = (float*)(smem + EXP_S);
    float* sM  = (float*)(smem + EXP_M);
    float* sH  = (float*)(smem + EXP_H);

    const int r0 = slab * 16 + (l >> 2);
    const int r1 = r0 + 8;

    if (kh == 1) {
        #pragma unroll
        for (int t = 0; t < 8; ++t) {
            float* dst = (t < 4) ? sFO : sS;
            const int c0 = (t & 3) * 8 + (l & 3) * 2;
            dst[r0 * 33 + c0]     = acc[t][0];
            dst[r0 * 33 + c0 + 1] = acc[t][1];
            dst[r1 * 33 + c0]     = acc[t][2];
            dst[r1 * 33 + c0 + 1] = acc[t][3];
        }
    }
    for (int i = tid; i < 1024; i += THREADS) {
        sM[i]        = lin1_w[i];
        sM[1056 + i] = lin2_w[i];
    }
    if (tid < 32) {
        sM[1024 + tid] = lin1_b[tid];
        sM[2080 + tid] = lin2_b[tid];
        sM[2112 + tid] = last_w[tid];
    }
    if (tid == 0) sM[2144] = last_b[0];
    __syncthreads();

    if (kh == 0) {
        #pragma unroll
        for (int t = 0; t < 8; ++t) {
            float* dst = (t < 4) ? sFO : sS;
            const int c0 = (t & 3) * 8 + (l & 3) * 2;
            dst[r0 * 33 + c0]     += acc[t][0];
            dst[r0 * 33 + c0 + 1] += acc[t][1];
            dst[r1 * 33 + c0]     += acc[t][2];
            dst[r1 * 33 + c0 + 1] += acc[t][3];
        }
    }
    __syncthreads();

    // ---- MLP: 4 threads per row, 8 outputs each ----
    const int mrow = tid >> 2;
    const int mo   = tid & 3;

    float xr[32];
    #pragma unroll
    for (int j = 0; j < 32; ++j) {
        float s = sS[mrow * 33 + j];
        xr[j] = fmaf(s, s, sFO[mrow * 33 + j]);
    }
    #pragma unroll
    for (int i = 0; i < 8; ++i) {
        int oi = mo * 8 + i;
        float t = sM[1024 + oi];
        #pragma unroll
        for (int j4 = 0; j4 < 8; ++j4) {
            float4 w = *(const float4*)&sM[oi * 32 + j4 * 4];
            t = fmaf(xr[j4 * 4],     w.x, t);
            t = fmaf(xr[j4 * 4 + 1], w.y, t);
            t = fmaf(xr[j4 * 4 + 2], w.z, t);
            t = fmaf(xr[j4 * 4 + 3], w.w, t);
        }
        sH[mrow * 33 + oi] = fmaxf(t, 0.f);
    }
    __syncthreads();

    float hr[32];
    #pragma unroll
    for (int j = 0; j < 32; ++j) hr[j] = sH[mrow * 33 + j];
    #pragma unroll
    for (int i = 0; i < 8; ++i) {
        int oi = mo * 8 + i;
        float t = sM[2080 + oi];
        #pragma unroll
        for (int j4 = 0; j4 < 8; ++j4) {
            float4 w = *(const float4*)&sM[1056 + oi * 32 + j4 * 4];
            t = fmaf(hr[j4 * 4],     w.x, t);
            t = fmaf(hr[j4 * 4 + 1], w.y, t);
            t = fmaf(hr[j4 * 4 + 2], w.z, t);
            t = fmaf(hr[j4 * 4 + 3], w.w, t);
        }
        sFO[mrow * 33 + oi] = fmaxf(t, 0.f);   // reuse sFO for h2
    }
    __syncthreads();

    if (mo == 0) {
        float o = sM[2144];
        #pragma unroll
        for (int j = 0; j < 32; ++j) o = fmaf(sFO[mrow * 33 + j], sM[2112 + j], o);
        out[b0 + mrow] = o;
    }
}

extern "C" void kernel_launch(void* const* d_in, const int* in_sizes, int n_in,
                              void* d_out, int out_size) {
    const int*   Xi     = (const int*)  d_in[0];
    const float* Xv     = (const float*)d_in[1];
    const float* tables = (const float*)d_in[2];
    const float* W1     = (const float*)d_in[3];
    const float* Wi     = (const float*)d_in[4];
    const float* lin1_w = (const float*)d_in[5];
    const float* lin1_b = (const float*)d_in[6];
    const float* lin2_w = (const float*)d_in[7];
    const float* lin2_b = (const float*)d_in[8];
    const float* last_w = (const float*)d_in[9];
    const float* last_b = (const float*)d_in[10];
    float* out = (float*)d_out;

    static bool attr_set = false;
    if (!attr_set) {
        cudaFuncSetAttribute(pnn_kernel, cudaFuncAttributeMaxDynamicSharedMemorySize, SMEM_BYTES);
        attr_set = true;
    }

    prep_kernel<<<(10 * 2 * 4 * 4 * 32 * 4 + 255) / 256, 256>>>(W1, Wi);
    pnn_kernel<<<BATCH / ROWSPB, THREADS, SMEM_BYTES>>>(
        Xi, Xv, tables, lin1_w, lin1_b, lin2_w, lin2_b, last_w, last_b, out);
}

// round 14
// speedup vs baseline: 1.7392x; 1.7392x over previous
#include <cuda_runtime.h>
#include <cuda_bf16.h>
#include <cstdint>

#define NFIELD 39
#define VOCAB  200000
#define BATCH  16384
#define ROWSPB 128
#define THREADS 256
#define NCHUNK 10          // 10 chunks x 4 fields (kstep16) = 640 padded k

// B fragments, chunk-major: [chunk10][hl2][s4][tp4][lane32][4 u32] = 160KB
__device__ __align__(16) uint32_t BfragG[10 * 2 * 4 * 4 * 32 * 4];
// MLP weight fragments: [layer2][hl2][ks2][nt4][lane32][2 u32] = 8KB
__device__ __align__(16) uint32_t MlpFragG[2 * 2 * 2 * 4 * 32 * 2];

__global__ void prep_kernel(const float* __restrict__ W1, const float* __restrict__ Wi) {
    int i = blockIdx.x * blockDim.x + threadIdx.x;
    if (i >= 10 * 2 * 4 * 4 * 32 * 4) return;
    int reg = i & 3;
    int l   = (i >> 2) & 31;
    int tp  = (i >> 7) & 3;
    int s   = (i >> 9) & 3;
    int hl  = (i >> 11) & 1;
    int c   = i >> 12;
    int gs = c * 4 + s;
    int t  = tp * 2 + (reg >> 1);
    int n  = t * 8 + (l >> 2);
    int k0 = gs * 16 + (l & 3) * 2 + (reg & 1) * 8;
    float v0 = 0.f, v1 = 0.f;
    if (k0 < 624)     v0 = (n < 32) ? W1[n * 624 + k0]     : Wi[(n - 32) * 624 + k0];
    if (k0 + 1 < 624) v1 = (n < 32) ? W1[n * 624 + k0 + 1] : Wi[(n - 32) * 624 + k0 + 1];
    float h0 = __bfloat162float(__float2bfloat16(v0));
    float h1 = __bfloat162float(__float2bfloat16(v1));
    uint32_t w;
    if (hl == 0) {
        asm("cvt.rn.bf16x2.f32 %0, %1, %2;" : "=r"(w) : "f"(h1), "f"(h0));
    } else {
        float r0 = v0 - h0, r1 = v1 - h1;
        asm("cvt.rn.bf16x2.f32 %0, %1, %2;" : "=r"(w) : "f"(r1), "f"(r0));
    }
    BfragG[i] = w;
}

__global__ void prep_mlp_kernel(const float* __restrict__ lin1_w, const float* __restrict__ lin2_w) {
    int i = blockIdx.x * blockDim.x + threadIdx.x;
    if (i >= 2048) return;
    int reg = i & 1;
    int l   = (i >> 1) & 31;
    int nt  = (i >> 6) & 3;
    int ks  = (i >> 8) & 1;
    int hl  = (i >> 9) & 1;
    int L   = (i >> 10) & 1;
    int n = nt * 8 + (l >> 2);
    int k = ks * 16 + (l & 3) * 2 + reg * 8;
    const float* W = L ? lin2_w : lin1_w;
    float v0 = W[n * 32 + k];
    float v1 = W[n * 32 + k + 1];
    float h0 = __bfloat162float(__float2bfloat16(v0));
    float h1 = __bfloat162float(__float2bfloat16(v1));
    uint32_t w;
    if (hl == 0) {
        asm("cvt.rn.bf16x2.f32 %0, %1, %2;" : "=r"(w) : "f"(h1), "f"(h0));
    } else {
        float r0 = v0 - h0, r1 = v1 - h1;
        asm("cvt.rn.bf16x2.f32 %0, %1, %2;" : "=r"(w) : "f"(r1), "f"(r0));
    }
    MlpFragG[i] = w;
}

__device__ __forceinline__ uint32_t packbf(float lo_elem, float hi_elem) {
    uint32_t r;
    asm("cvt.rn.bf16x2.f32 %0, %1, %2;" : "=r"(r) : "f"(hi_elem), "f"(lo_elem));
    return r;
}
__device__ __forceinline__ void mma16816(float* d, uint32_t a0, uint32_t a1, uint32_t a2, uint32_t a3,
                                         uint32_t b0, uint32_t b1) {
    asm volatile("mma.sync.aligned.m16n8k16.row.col.f32.bf16.bf16.f32 "
                 "{%0,%1,%2,%3}, {%4,%5,%6,%7}, {%8,%9}, {%0,%1,%2,%3};"
                 : "+f"(d[0]), "+f"(d[1]), "+f"(d[2]), "+f"(d[3])
                 : "r"(a0), "r"(a1), "r"(a2), "r"(a3), "r"(b0), "r"(b1));
}
__device__ __forceinline__ void ldsm4(uint32_t& r0, uint32_t& r1, uint32_t& r2, uint32_t& r3,
                                      uint32_t addr) {
    asm volatile("ldmatrix.sync.aligned.m8n8.x4.shared.b16 {%0,%1,%2,%3}, [%4];"
                 : "=r"(r0), "=r"(r1), "=r"(r2), "=r"(r3) : "r"(addr));
}
__device__ __forceinline__ void pair_bar(int id) {
    asm volatile("bar.sync %0, %1;" :: "r"(id), "r"(64) : "memory");
}

// smem (64KB): A only: [pair4][buf2][hl2][s4][m2 x 512B]
#define SMEM_BYTES 65536
// epilogue aliases:
#define EXP_FO 0        // 128 x 33 floats (16896B)
#define EXP_S  16896    // 128 x 33 floats
#define EXP_X  33792    // x bf16 hi/lo ldsm tiles: [slab8][2048B] = 16384B
#define EXP_M  50176    // small consts: lin1_b[32], lin2_b[32], last_w[32], last_b

__global__ __launch_bounds__(THREADS, 1)
void pnn_kernel(const int*   __restrict__ Xi,
                const float* __restrict__ Xv,
                const float* __restrict__ tables,
                const float* __restrict__ lin1_b,
                const float* __restrict__ lin2_b,
                const float* __restrict__ last_w,
                const float* __restrict__ last_b,
                float*       __restrict__ out) {
    extern __shared__ unsigned char smem[];
    const uint32_t sbase = (uint32_t)__cvta_generic_to_shared(smem);

    const int tid = threadIdx.x;
    const int wid = tid >> 5;
    const int l   = tid & 31;
    const int b0  = blockIdx.x * ROWSPB;

    const int p  = wid >> 1;
    const int nh = wid & 1;
    const uint32_t apair = (uint32_t)(p * 16384);

    const int pt = tid & 63;
    const int qi = pt >> 2;
    const int q  = pt & 3;

    int    nidx[3][8];
    float  nxv[3][8];
    float4 tdat[2][8];

    float acc[2][4][4];
    #pragma unroll
    for (int m = 0; m < 2; ++m)
        #pragma unroll
        for (int t = 0; t < 4; ++t)
            #pragma unroll
            for (int r = 0; r < 4; ++r) acc[m][t][r] = 0.f;

    const uint4* __restrict__ Bp = (const uint4*)BfragG;

    auto load_idx = [&](int c, int slot) {
        #pragma unroll
        for (int it = 0; it < 8; ++it) {
            int rl = (it >> 2) * 16 + qi;
            int f  = c * 4 + (it & 3);
            int row = b0 + p * 32 + rl;
            if (f < NFIELD) {
                nidx[slot][it] = Xi[(size_t)row * NFIELD + f];
                nxv[slot][it]  = Xv[(size_t)row * NFIELD + f];
            } else {
                nidx[slot][it] = 0;
                nxv[slot][it]  = 0.f;
            }
        }
    };
    auto table_ldg = [&](int c) {
        const int islot = c % 3, tslot = c & 1;
        #pragma unroll
        for (int it = 0; it < 8; ++it) {
            int f = c * 4 + (it & 3);
            if (f < NFIELD)
                tdat[tslot][it] = *(((const float4*)tables) + ((long)f * VOCAB + nidx[islot][it]) * 4 + q);
            else
                tdat[tslot][it] = make_float4(0.f, 0.f, 0.f, 0.f);
        }
    };
    auto cv_store = [&](int c) {
        const int islot = c % 3, tslot = c & 1;
        const uint32_t bufo = apair + (uint32_t)((c & 1) * 8192);
        #pragma unroll
        for (int it = 0; it < 8; ++it) {
            int rl = (it >> 2) * 16 + qi;
            int j  = it & 3;
            float xv = nxv[islot][it];
            float4 t4 = tdat[tslot][it];
            float v0 = t4.x * xv, v1 = t4.y * xv, v2 = t4.z * xv, v3 = t4.w * xv;
            float r0 = v0 - __bfloat162float(__float2bfloat16(v0));
            float r1 = v1 - __bfloat162float(__float2bfloat16(v1));
            float r2 = v2 - __bfloat162float(__float2bfloat16(v2));
            float r3 = v3 - __bfloat162float(__float2bfloat16(v3));
            uint32_t inoff = (uint32_t)((rl >> 4) * 512 + (q >> 1) * 256 + (rl & 15) * 16 + (q & 1) * 8);
            unsigned char* bh = smem + bufo + (0 * 4 + j) * 1024 + inoff;
            unsigned char* bl = smem + bufo + (4 + j) * 1024 + inoff;
            *(uint2*)bh = make_uint2(packbf(v0, v1), packbf(v2, v3));
            *(uint2*)bl = make_uint2(packbf(r0, r1), packbf(r2, r3));
        }
    };
    auto do_mma = [&](int c) {
        const uint32_t abase = sbase + apair + (uint32_t)((c & 1) * 8192);
        const uint32_t laddr = (uint32_t)((l & 15) * 16 + (l >> 4) * 256);
        #pragma unroll
        for (int s = 0; s < 4; ++s) {
            uint4 Bh0 = Bp[c * 1024 + 0 * 512 + s * 128 + (nh * 2 + 0) * 32 + l];
            uint4 Bh1 = Bp[c * 1024 + 0 * 512 + s * 128 + (nh * 2 + 1) * 32 + l];
            uint4 Bl0 = Bp[c * 1024 + 1 * 512 + s * 128 + (nh * 2 + 0) * 32 + l];
            uint4 Bl1 = Bp[c * 1024 + 1 * 512 + s * 128 + (nh * 2 + 1) * 32 + l];
            #pragma unroll
            for (int m = 0; m < 2; ++m) {
                uint32_t ah0, ah1, ah2, ah3, al0, al1, al2, al3;
                ldsm4(ah0, ah1, ah2, ah3, abase + (0 * 4 + s) * 1024 + m * 512 + laddr);
                ldsm4(al0, al1, al2, al3, abase + (4 + s) * 1024 + m * 512 + laddr);
                mma16816(acc[m][0], ah0, ah1, ah2, ah3, Bh0.x, Bh0.y);
                mma16816(acc[m][1], ah0, ah1, ah2, ah3, Bh0.z, Bh0.w);
                mma16816(acc[m][2], ah0, ah1, ah2, ah3, Bh1.x, Bh1.y);
                mma16816(acc[m][3], ah0, ah1, ah2, ah3, Bh1.z, Bh1.w);
                mma16816(acc[m][0], ah0, ah1, ah2, ah3, Bl0.x, Bl0.y);
                mma16816(acc[m][1], ah0, ah1, ah2, ah3, Bl0.z, Bl0.w);
                mma16816(acc[m][2], ah0, ah1, ah2, ah3, Bl1.x, Bl1.y);
                mma16816(acc[m][3], ah0, ah1, ah2, ah3, Bl1.z, Bl1.w);
                mma16816(acc[m][0], al0, al1, al2, al3, Bh0.x, Bh0.y);
                mma16816(acc[m][1], al0, al1, al2, al3, Bh0.z, Bh0.w);
                mma16816(acc[m][2], al0, al1, al2, al3, Bh1.x, Bh1.y);
                mma16816(acc[m][3], al0, al1, al2, al3, Bh1.z, Bh1.w);
            }
        }
    };

    // ---- prologue ----
    load_idx(0, 0);
    load_idx(1, 1);
    load_idx(2, 2);
    table_ldg(0);
    table_ldg(1);
    cv_store(0);
    pair_bar(p + 1);

    // ---- free-running pipelined loop (pair-local sync only) ----
    #pragma unroll
    for (int c = 0; c < NCHUNK; ++c) {
        if (c + 3 < NCHUNK) load_idx(c + 3, (c + 3) % 3);
        if (c + 2 < NCHUNK) table_ldg(c + 2);
        do_mma(c);
        if (c + 1 < NCHUNK) cv_store(c + 1);
        if (c + 1 < NCHUNK) pair_bar(p + 1);
    }
    __syncthreads();

    // ---- epilogue ----
    float* sFO = (float*)(smem + EXP_FO);
    float* sS  = (float*)(smem + EXP_S);
    unsigned char* sX = smem + EXP_X;
    float* sM  = (float*)(smem + EXP_M);

    {
        float* dst = nh ? sS : sFO;
        #pragma unroll
        for (int m = 0; m < 2; ++m) {
            const int r0 = p * 32 + m * 16 + (l >> 2);
            const int r1 = r0 + 8;
            #pragma unroll
            for (int t = 0; t < 4; ++t) {
                const int c0 = t * 8 + (l & 3) * 2;
                dst[r0 * 33 + c0]     = acc[m][t][0];
                dst[r0 * 33 + c0 + 1] = acc[m][t][1];
                dst[r1 * 33 + c0]     = acc[m][t][2];
                dst[r1 * 33 + c0 + 1] = acc[m][t][3];
            }
        }
    }
    if (tid < 32) {
        sM[tid]      = lin1_b[tid];
        sM[32 + tid] = lin2_b[tid];
        sM[64 + tid] = last_w[tid];
    }
    if (tid == 0) sM[96] = last_b[0];
    __syncthreads();

    // combine x = fo + s^2 -> bf16 hi/lo ldsm tiles
    {
        const int r  = tid >> 1;
        const int jb = (tid & 1) * 16;
        const int sl = r >> 4, rl = r & 15;
        float xv16[16];
        #pragma unroll
        for (int j = 0; j < 16; ++j) {
            float fo = sFO[r * 33 + jb + j];
            float s  = sS [r * 33 + jb + j];
            xv16[j] = fmaf(s, s, fo);
        }
        uint32_t hiw[8], low[8];
        #pragma unroll
        for (int j2 = 0; j2 < 8; ++j2) {
            float v0 = xv16[2 * j2], v1 = xv16[2 * j2 + 1];
            float h0f = __bfloat162float(__float2bfloat16(v0));
            float h1f = __bfloat162float(__float2bfloat16(v1));
            hiw[j2] = packbf(v0, v1);
            low[j2] = packbf(v0 - h0f, v1 - h1f);
        }
        #pragma unroll
        for (int g = 0; g < 2; ++g) {
            int j0 = jb + g * 8;
            uint32_t off = (uint32_t)(sl * 2048 + (j0 >> 4) * 512 + ((j0 >> 3) & 1) * 256 + rl * 16);
            *(uint4*)(sX + off)        = make_uint4(hiw[g*4], hiw[g*4+1], hiw[g*4+2], hiw[g*4+3]);
            *(uint4*)(sX + off + 1024) = make_uint4(low[g*4], low[g*4+1], low[g*4+2], low[g*4+3]);
        }
    }
    __syncthreads();

    // ---- MLP via MMA: warp -> slab ----
    {
        const int slab = wid;
        const uint32_t xbase = sbase + (uint32_t)(EXP_X + slab * 2048);
        const uint32_t laddr = (uint32_t)((l & 15) * 16 + (l >> 4) * 256);
        const uint2* __restrict__ Mf = (const uint2*)MlpFragG;

        uint32_t axh[2][4], axl[2][4];
        ldsm4(axh[0][0], axh[0][1], axh[0][2], axh[0][3], xbase + 0 * 512 + laddr);
        ldsm4(axh[1][0], axh[1][1], axh[1][2], axh[1][3], xbase + 1 * 512 + laddr);
        ldsm4(axl[0][0], axl[0][1], axl[0][2], axl[0][3], xbase + 1024 + 0 * 512 + laddr);
        ldsm4(axl[1][0], axl[1][1], axl[1][2], axl[1][3], xbase + 1024 + 1 * 512 + laddr);

        // layer 1 (bias in accumulator)
        float a1[4][4];
        #pragma unroll
        for (int nt = 0; nt < 4; ++nt) {
            int c0 = nt * 8 + (l & 3) * 2;
            float blo = sM[c0], bhi = sM[c0 + 1];
            a1[nt][0] = blo; a1[nt][1] = bhi; a1[nt][2] = blo; a1[nt][3] = bhi;
        }
        #pragma unroll
        for (int ks = 0; ks < 2; ++ks)
            #pragma unroll
            for (int nt = 0; nt < 4; ++nt) {
                uint2 Bh = Mf[(((0 * 2 + 0) * 2 + ks) * 4 + nt) * 32 + l];
                uint2 Bl = Mf[(((0 * 2 + 1) * 2 + ks) * 4 + nt) * 32 + l];
                mma16816(a1[nt], axh[ks][0], axh[ks][1], axh[ks][2], axh[ks][3], Bh.x, Bh.y);
                mma16816(a1[nt], axh[ks][0], axh[ks][1], axh[ks][2], axh[ks][3], Bl.x, Bl.y);
                mma16816(a1[nt], axl[ks][0], axl[ks][1], axl[ks][2], axl[ks][3], Bh.x, Bh.y);
            }
        #pragma unroll
        for (int nt = 0; nt < 4; ++nt)
            #pragma unroll
            for (int r = 0; r < 4; ++r) a1[nt][r] = fmaxf(a1[nt][r], 0.f);

        // h1 D-frags -> layer-2 A-frags (hi + lo)
        uint32_t bh2[2][4], bl2[2][4];
        #pragma unroll
        for (int ks = 0; ks < 2; ++ks) {
            const float* d0 = a1[ks * 2];
            const float* d1 = a1[ks * 2 + 1];
            bh2[ks][0] = packbf(d0[0], d0[1]);
            bh2[ks][1] = packbf(d0[2], d0[3]);
            bh2[ks][2] = packbf(d1[0], d1[1]);
            bh2[ks][3] = packbf(d1[2], d1[3]);
            float r00 = d0[0] - __bfloat162float(__float2bfloat16(d0[0]));
            float r01 = d0[1] - __bfloat162float(__float2bfloat16(d0[1]));
            float r02 = d0[2] - __bfloat162float(__float2bfloat16(d0[2]));
            float r03 = d0[3] - __bfloat162float(__float2bfloat16(d0[3]));
            float r10 = d1[0] - __bfloat162float(__float2bfloat16(d1[0]));
            float r11 = d1[1] - __bfloat162float(__float2bfloat16(d1[1]));
            float r12 = d1[2] - __bfloat162float(__float2bfloat16(d1[2]));
            float r13 = d1[3] - __bfloat162float(__float2bfloat16(d1[3]));
            bl2[ks][0] = packbf(r00, r01);
            bl2[ks][1] = packbf(r02, r03);
            bl2[ks][2] = packbf(r10, r11);
            bl2[ks][3] = packbf(r12, r13);
        }

        // layer 2
        float a2[4][4];
        #pragma unroll
        for (int nt = 0; nt < 4; ++nt) {
            int c0 = nt * 8 + (l & 3) * 2;
            float blo = sM[32 + c0], bhi = sM[32 + c0 + 1];
            a2[nt][0] = blo; a2[nt][1] = bhi; a2[nt][2] = blo; a2[nt][3] = bhi;
        }
        #pragma unroll
        for (int ks = 0; ks < 2; ++ks)
            #pragma unroll
            for (int nt = 0; nt < 4; ++nt) {
                uint2 Bh = Mf[(((1 * 2 + 0) * 2 + ks) * 4 + nt) * 32 + l];
                uint2 Bl = Mf[(((1 * 2 + 1) * 2 + ks) * 4 + nt) * 32 + l];
                mma16816(a2[nt], bh2[ks][0], bh2[ks][1], bh2[ks][2], bh2[ks][3], Bh.x, Bh.y);
                mma16816(a2[nt], bh2[ks][0], bh2[ks][1], bh2[ks][2], bh2[ks][3], Bl.x, Bl.y);
                mma16816(a2[nt], bl2[ks][0], bl2[ks][1], bl2[ks][2], bl2[ks][3], Bh.x, Bh.y);
            }

        // final layer: relu(h2) . last_w, reduce across quad
        float s0 = 0.f, s1 = 0.f;
        #pragma unroll
        for (int nt = 0; nt < 4; ++nt) {
            int c0 = nt * 8 + (l & 3) * 2;
            float lw0 = sM[64 + c0], lw1 = sM[64 + c0 + 1];
            s0 = fmaf(fmaxf(a2[nt][0], 0.f), lw0, s0);
            s0 = fmaf(fmaxf(a2[nt][1], 0.f), lw1, s0);
            s1 = fmaf(fmaxf(a2[nt][2], 0.f), lw0, s1);
            s1 = fmaf(fmaxf(a2[nt][3], 0.f), lw1, s1);
        }
        s0 += __shfl_xor_sync(0xffffffff, s0, 1);
        s0 += __shfl_xor_sync(0xffffffff, s0, 2);
        s1 += __shfl_xor_sync(0xffffffff, s1, 1);
        s1 += __shfl_xor_sync(0xffffffff, s1, 2);
        if ((l & 3) == 0) {
            float lb = sM[96];
            out[b0 + slab * 16 + (l >> 2)]     = s0 + lb;
            out[b0 + slab * 16 + (l >> 2) + 8] = s1 + lb;
        }
    }
}

extern "C" void kernel_launch(void* const* d_in, const int* in_sizes, int n_in,
                              void* d_out, int out_size) {
    const int*   Xi     = (const int*)  d_in[0];
    const float* Xv     = (const float*)d_in[1];
    const float* tables = (const float*)d_in[2];
    const float* W1     = (const float*)d_in[3];
    const float* Wi     = (const float*)d_in[4];
    const float* lin1_w = (const float*)d_in[5];
    const float* lin1_b = (const float*)d_in[6];
    const float* lin2_w = (const float*)d_in[7];
    const float* lin2_b = (const float*)d_in[8];
    const float* last_w = (const float*)d_in[9];
    const float* last_b = (const float*)d_in[10];
    float* out = (float*)d_out;

    static bool attr_set = false;
    if (!attr_set) {
        cudaFuncSetAttribute(pnn_kernel, cudaFuncAttributeMaxDynamicSharedMemorySize, SMEM_BYTES);
        attr_set = true;
    }

    prep_kernel<<<(10 * 2 * 4 * 4 * 32 * 4 + 255) / 256, 256>>>(W1, Wi);
    prep_mlp_kernel<<<8, 256>>>(lin1_w, lin2_w);
    pnn_kernel<<<BATCH / ROWSPB, THREADS, SMEM_BYTES>>>(
        Xi, Xv, tables, lin1_b, lin2_b, last_w, last_b, out);
}

// round 16
// speedup vs baseline: 1.8775x; 1.0795x over previous
#include <cuda_runtime.h>
#include <cuda_bf16.h>
#include <cstdint>

#define NFIELD 39
#define VOCAB  200000
#define BATCH  16384
#define ROWSPB 128
#define THREADS 256
#define NCHUNK 10          // 10 chunks x 4 fields (kstep16) = 640 padded k

// B fragments, chunk-major: [chunk10][hl2][s4][tp4][lane32][4 u32] = 160KB
__device__ __align__(16) uint32_t BfragG[10 * 2 * 4 * 4 * 32 * 4];
// MLP weight fragments: [layer2][hl2][ks2][nt4][lane32][2 u32] = 8KB
__device__ __align__(16) uint32_t MlpFragG[2 * 2 * 2 * 4 * 32 * 2];

// Merged prep: each thread computes its W element pair ONCE, emits hi AND lo words.
//   j in [0, 20480): B frags, enumerated over [c10][s4][tp4][l32][reg4]
//   j in [20480, 21504): MLP frags, over [L2][ks2][nt4][l32][reg2]
// Consumer indexing (authoritative):
//   BfragG  [ ((((c*2+hl)*4+s)*4+tp)*32+l)*4+reg ]  -> hl stride = 4*4*32*4 = 2048 u32
//   MlpFragG[ ((((L*2+hl)*2+ks)*4+nt)*32+l)*2+reg ] -> hl stride = 2*4*32*2 = 512 u32
__global__ void prep_all_kernel(const float* __restrict__ W1, const float* __restrict__ Wi,
                                const float* __restrict__ lin1_w, const float* __restrict__ lin2_w) {
    int j = blockIdx.x * blockDim.x + threadIdx.x;
    if (j < 20480) {
        int reg = j & 3;
        int l   = (j >> 2) & 31;
        int tp  = (j >> 7) & 3;
        int s   = (j >> 9) & 3;
        int c   = j >> 11;
        int gs = c * 4 + s;
        int t  = tp * 2 + (reg >> 1);
        int n  = t * 8 + (l >> 2);
        int k0 = gs * 16 + (l & 3) * 2 + (reg & 1) * 8;
        float v0 = 0.f, v1 = 0.f;
        if (k0 < 624)     v0 = (n < 32) ? W1[n * 624 + k0]     : Wi[(n - 32) * 624 + k0];
        if (k0 + 1 < 624) v1 = (n < 32) ? W1[n * 624 + k0 + 1] : Wi[(n - 32) * 624 + k0 + 1];
        float h0 = __bfloat162float(__float2bfloat16(v0));
        float h1 = __bfloat162float(__float2bfloat16(v1));
        uint32_t whi, wlo;
        asm("cvt.rn.bf16x2.f32 %0, %1, %2;" : "=r"(whi) : "f"(h1), "f"(h0));
        float r0 = v0 - h0, r1 = v1 - h1;
        asm("cvt.rn.bf16x2.f32 %0, %1, %2;" : "=r"(wlo) : "f"(r1), "f"(r0));
        // hl=0 base: (((c*2+0)*4+s)*4+tp)*128 + l*4 + reg
        int base = (((c * 2) * 4 + s) * 4 + tp) * 128 + l * 4 + reg;
        BfragG[base]        = whi;
        BfragG[base + 2048] = wlo;    // hl=1 plane: +4*4*32*4
    } else if (j < 21504) {
        int j2 = j - 20480;
        int reg = j2 & 1;
        int l   = (j2 >> 1) & 31;
        int nt  = (j2 >> 6) & 3;
        int ks  = (j2 >> 8) & 1;
        int L   = (j2 >> 9) & 1;
        int n = nt * 8 + (l >> 2);
        int k = ks * 16 + (l & 3) * 2 + reg * 8;
        const float* W = L ? lin2_w : lin1_w;
        float v0 = W[n * 32 + k];
        float v1 = W[n * 32 + k + 1];
        float h0 = __bfloat162float(__float2bfloat16(v0));
        float h1 = __bfloat162float(__float2bfloat16(v1));
        uint32_t whi, wlo;
        asm("cvt.rn.bf16x2.f32 %0, %1, %2;" : "=r"(whi) : "f"(h1), "f"(h0));
        float r0 = v0 - h0, r1 = v1 - h1;
        asm("cvt.rn.bf16x2.f32 %0, %1, %2;" : "=r"(wlo) : "f"(r1), "f"(r0));
        // hl=0 base: (((L*2+0)*2+ks)*4+nt)*64 + l*2 + reg
        int base = (((L * 2) * 2 + ks) * 4 + nt) * 64 + l * 2 + reg;
        MlpFragG[base]       = whi;
        MlpFragG[base + 512] = wlo;   // hl=1 plane: +2*4*32*2
    }
}

__device__ __forceinline__ uint32_t packbf(float lo_elem, float hi_elem) {
    uint32_t r;
    asm("cvt.rn.bf16x2.f32 %0, %1, %2;" : "=r"(r) : "f"(hi_elem), "f"(lo_elem));
    return r;
}
__device__ __forceinline__ void mma16816(float* d, uint32_t a0, uint32_t a1, uint32_t a2, uint32_t a3,
                                         uint32_t b0, uint32_t b1) {
    asm volatile("mma.sync.aligned.m16n8k16.row.col.f32.bf16.bf16.f32 "
                 "{%0,%1,%2,%3}, {%4,%5,%6,%7}, {%8,%9}, {%0,%1,%2,%3};"
                 : "+f"(d[0]), "+f"(d[1]), "+f"(d[2]), "+f"(d[3])
                 : "r"(a0), "r"(a1), "r"(a2), "r"(a3), "r"(b0), "r"(b1));
}
__device__ __forceinline__ void ldsm4(uint32_t& r0, uint32_t& r1, uint32_t& r2, uint32_t& r3,
                                      uint32_t addr) {
    asm volatile("ldmatrix.sync.aligned.m8n8.x4.shared.b16 {%0,%1,%2,%3}, [%4];"
                 : "=r"(r0), "=r"(r1), "=r"(r2), "=r"(r3) : "r"(addr));
}
__device__ __forceinline__ void pair_bar(int id) {
    asm volatile("bar.sync %0, %1;" :: "r"(id), "r"(64) : "memory");
}

// smem (64KB): A only: [pair4][buf2][hl2][s4][m2 x 512B]
#define SMEM_BYTES 65536
#define EXP_FO 0
#define EXP_S  16896
#define EXP_X  33792
#define EXP_M  50176

__global__ __launch_bounds__(THREADS, 1)
void pnn_kernel(const int*   __restrict__ Xi,
                const float* __restrict__ Xv,
                const float* __restrict__ tables,
                const float* __restrict__ lin1_b,
                const float* __restrict__ lin2_b,
                const float* __restrict__ last_w,
                const float* __restrict__ last_b,
                float*       __restrict__ out) {
    extern __shared__ unsigned char smem[];
    const uint32_t sbase = (uint32_t)__cvta_generic_to_shared(smem);

    const int tid = threadIdx.x;
    const int wid = tid >> 5;
    const int l   = tid & 31;
    const int b0  = blockIdx.x * ROWSPB;

    const int p  = wid >> 1;
    const int nh = wid & 1;
    const uint32_t apair = (uint32_t)(p * 16384);

    const int pt = tid & 63;
    const int qi = pt >> 2;
    const int q  = pt & 3;

    int    nidx[3][8];
    float  nxv[3][8];
    float4 tdat[2][8];

    float acc[2][4][4];
    #pragma unroll
    for (int m = 0; m < 2; ++m)
        #pragma unroll
        for (int t = 0; t < 4; ++t)
            #pragma unroll
            for (int r = 0; r < 4; ++r) acc[m][t][r] = 0.f;

    const uint4* __restrict__ Bp = (const uint4*)BfragG;

    auto load_idx = [&](int c, int slot) {
        #pragma unroll
        for (int it = 0; it < 8; ++it) {
            int rl = (it >> 2) * 16 + qi;
            int f  = c * 4 + (it & 3);
            int row = b0 + p * 32 + rl;
            if (f < NFIELD) {
                nidx[slot][it] = Xi[(size_t)row * NFIELD + f];
                nxv[slot][it]  = Xv[(size_t)row * NFIELD + f];
            } else {
                nidx[slot][it] = 0;
                nxv[slot][it]  = 0.f;
            }
        }
    };
    auto table_ldg = [&](int c) {
        const int islot = c % 3, tslot = c & 1;
        #pragma unroll
        for (int it = 0; it < 8; ++it) {
            int f = c * 4 + (it & 3);
            if (f < NFIELD)
                tdat[tslot][it] = *(((const float4*)tables) + ((long)f * VOCAB + nidx[islot][it]) * 4 + q);
            else
                tdat[tslot][it] = make_float4(0.f, 0.f, 0.f, 0.f);
        }
    };
    auto cv_store = [&](int c) {
        const int islot = c % 3, tslot = c & 1;
        const uint32_t bufo = apair + (uint32_t)((c & 1) * 8192);
        #pragma unroll
        for (int it = 0; it < 8; ++it) {
            int rl = (it >> 2) * 16 + qi;
            int j  = it & 3;
            float xv = nxv[islot][it];
            float4 t4 = tdat[tslot][it];
            float v0 = t4.x * xv, v1 = t4.y * xv, v2 = t4.z * xv, v3 = t4.w * xv;
            float r0 = v0 - __bfloat162float(__float2bfloat16(v0));
            float r1 = v1 - __bfloat162float(__float2bfloat16(v1));
            float r2 = v2 - __bfloat162float(__float2bfloat16(v2));
            float r3 = v3 - __bfloat162float(__float2bfloat16(v3));
            uint32_t inoff = (uint32_t)((rl >> 4) * 512 + (q >> 1) * 256 + (rl & 15) * 16 + (q & 1) * 8);
            unsigned char* bh = smem + bufo + (0 * 4 + j) * 1024 + inoff;
            unsigned char* bl = smem + bufo + (4 + j) * 1024 + inoff;
            *(uint2*)bh = make_uint2(packbf(v0, v1), packbf(v2, v3));
            *(uint2*)bl = make_uint2(packbf(r0, r1), packbf(r2, r3));
        }
    };
    auto do_mma = [&](int c) {
        const uint32_t abase = sbase + apair + (uint32_t)((c & 1) * 8192);
        const uint32_t laddr = (uint32_t)((l & 15) * 16 + (l >> 4) * 256);
        #pragma unroll
        for (int s = 0; s < 4; ++s) {
            uint4 Bh0 = Bp[c * 1024 + 0 * 512 + s * 128 + (nh * 2 + 0) * 32 + l];
            uint4 Bh1 = Bp[c * 1024 + 0 * 512 + s * 128 + (nh * 2 + 1) * 32 + l];
            uint4 Bl0 = Bp[c * 1024 + 1 * 512 + s * 128 + (nh * 2 + 0) * 32 + l];
            uint4 Bl1 = Bp[c * 1024 + 1 * 512 + s * 128 + (nh * 2 + 1) * 32 + l];
            #pragma unroll
            for (int m = 0; m < 2; ++m) {
                uint32_t ah0, ah1, ah2, ah3, al0, al1, al2, al3;
                ldsm4(ah0, ah1, ah2, ah3, abase + (0 * 4 + s) * 1024 + m * 512 + laddr);
                ldsm4(al0, al1, al2, al3, abase + (4 + s) * 1024 + m * 512 + laddr);
                mma16816(acc[m][0], ah0, ah1, ah2, ah3, Bh0.x, Bh0.y);
                mma16816(acc[m][1], ah0, ah1, ah2, ah3, Bh0.z, Bh0.w);
                mma16816(acc[m][2], ah0, ah1, ah2, ah3, Bh1.x, Bh1.y);
                mma16816(acc[m][3], ah0, ah1, ah2, ah3, Bh1.z, Bh1.w);
                mma16816(acc[m][0], ah0, ah1, ah2, ah3, Bl0.x, Bl0.y);
                mma16816(acc[m][1], ah0, ah1, ah2, ah3, Bl0.z, Bl0.w);
                mma16816(acc[m][2], ah0, ah1, ah2, ah3, Bl1.x, Bl1.y);
                mma16816(acc[m][3], ah0, ah1, ah2, ah3, Bl1.z, Bl1.w);
                mma16816(acc[m][0], al0, al1, al2, al3, Bh0.x, Bh0.y);
                mma16816(acc[m][1], al0, al1, al2, al3, Bh0.z, Bh0.w);
                mma16816(acc[m][2], al0, al1, al2, al3, Bh1.x, Bh1.y);
                mma16816(acc[m][3], al0, al1, al2, al3, Bh1.z, Bh1.w);
            }
        }
    };

    // ---- prologue ----
    load_idx(0, 0);
    load_idx(1, 1);
    load_idx(2, 2);
    table_ldg(0);
    table_ldg(1);
    cv_store(0);
    pair_bar(p + 1);

    #pragma unroll
    for (int c = 0; c < NCHUNK; ++c) {
        if (c + 3 < NCHUNK) load_idx(c + 3, (c + 3) % 3);
        if (c + 2 < NCHUNK) table_ldg(c + 2);
        do_mma(c);
        if (c + 1 < NCHUNK) cv_store(c + 1);
        if (c + 1 < NCHUNK) pair_bar(p + 1);
    }
    __syncthreads();

    // ---- epilogue ----
    float* sFO = (float*)(smem + EXP_FO);
    float* sS  = (float*)(smem + EXP_S);
    unsigned char* sX = smem + EXP_X;
    float* sM  = (float*)(smem + EXP_M);

    {
        float* dst = nh ? sS : sFO;
        #pragma unroll
        for (int m = 0; m < 2; ++m) {
            const int r0 = p * 32 + m * 16 + (l >> 2);
            const int r1 = r0 + 8;
            #pragma unroll
            for (int t = 0; t < 4; ++t) {
                const int c0 = t * 8 + (l & 3) * 2;
                dst[r0 * 33 + c0]     = acc[m][t][0];
                dst[r0 * 33 + c0 + 1] = acc[m][t][1];
                dst[r1 * 33 + c0]     = acc[m][t][2];
                dst[r1 * 33 + c0 + 1] = acc[m][t][3];
            }
        }
    }
    if (tid < 32) {
        sM[tid]      = lin1_b[tid];
        sM[32 + tid] = lin2_b[tid];
        sM[64 + tid] = last_w[tid];
    }
    if (tid == 0) sM[96] = last_b[0];
    __syncthreads();

    {
        const int r  = tid >> 1;
        const int jb = (tid & 1) * 16;
        const int sl = r >> 4, rl = r & 15;
        float xv16[16];
        #pragma unroll
        for (int j = 0; j < 16; ++j) {
            float fo = sFO[r * 33 + jb + j];
            float s  = sS [r * 33 + jb + j];
            xv16[j] = fmaf(s, s, fo);
        }
        uint32_t hiw[8], low[8];
        #pragma unroll
        for (int j2 = 0; j2 < 8; ++j2) {
            float v0 = xv16[2 * j2], v1 = xv16[2 * j2 + 1];
            float h0f = __bfloat162float(__float2bfloat16(v0));
            float h1f = __bfloat162float(__float2bfloat16(v1));
            hiw[j2] = packbf(v0, v1);
            low[j2] = packbf(v0 - h0f, v1 - h1f);
        }
        #pragma unroll
        for (int g = 0; g < 2; ++g) {
            int j0 = jb + g * 8;
            uint32_t off = (uint32_t)(sl * 2048 + (j0 >> 4) * 512 + ((j0 >> 3) & 1) * 256 + rl * 16);
            *(uint4*)(sX + off)        = make_uint4(hiw[g*4], hiw[g*4+1], hiw[g*4+2], hiw[g*4+3]);
            *(uint4*)(sX + off + 1024) = make_uint4(low[g*4], low[g*4+1], low[g*4+2], low[g*4+3]);
        }
    }
    __syncthreads();

    {
        const int slab = wid;
        const uint32_t xbase = sbase + (uint32_t)(EXP_X + slab * 2048);
        const uint32_t laddr = (uint32_t)((l & 15) * 16 + (l >> 4) * 256);
        const uint2* __restrict__ Mf = (const uint2*)MlpFragG;

        uint32_t axh[2][4], axl[2][4];
        ldsm4(axh[0][0], axh[0][1], axh[0][2], axh[0][3], xbase + 0 * 512 + laddr);
        ldsm4(axh[1][0], axh[1][1], axh[1][2], axh[1][3], xbase + 1 * 512 + laddr);
        ldsm4(axl[0][0], axl[0][1], axl[0][2], axl[0][3], xbase + 1024 + 0 * 512 + laddr);
        ldsm4(axl[1][0], axl[1][1], axl[1][2], axl[1][3], xbase + 1024 + 1 * 512 + laddr);

        float a1[4][4];
        #pragma unroll
        for (int nt = 0; nt < 4; ++nt) {
            int c0 = nt * 8 + (l & 3) * 2;
            float blo = sM[c0], bhi = sM[c0 + 1];
            a1[nt][0] = blo; a1[nt][1] = bhi; a1[nt][2] = blo; a1[nt][3] = bhi;
        }
        #pragma unroll
        for (int ks = 0; ks < 2; ++ks)
            #pragma unroll
            for (int nt = 0; nt < 4; ++nt) {
                uint2 Bh = Mf[(((0 * 2 + 0) * 2 + ks) * 4 + nt) * 32 + l];
                uint2 Bl = Mf[(((0 * 2 + 1) * 2 + ks) * 4 + nt) * 32 + l];
                mma16816(a1[nt], axh[ks][0], axh[ks][1], axh[ks][2], axh[ks][3], Bh.x, Bh.y);
                mma16816(a1[nt], axh[ks][0], axh[ks][1], axh[ks][2], axh[ks][3], Bl.x, Bl.y);
                mma16816(a1[nt], axl[ks][0], axl[ks][1], axl[ks][2], axl[ks][3], Bh.x, Bh.y);
            }
        #pragma unroll
        for (int nt = 0; nt < 4; ++nt)
            #pragma unroll
            for (int r = 0; r < 4; ++r) a1[nt][r] = fmaxf(a1[nt][r], 0.f);

        uint32_t bh2[2][4], bl2[2][4];
        #pragma unroll
        for (int ks = 0; ks < 2; ++ks) {
            const float* d0 = a1[ks * 2];
            const float* d1 = a1[ks * 2 + 1];
            bh2[ks][0] = packbf(d0[0], d0[1]);
            bh2[ks][1] = packbf(d0[2], d0[3]);
            bh2[ks][2] = packbf(d1[0], d1[1]);
            bh2[ks][3] = packbf(d1[2], d1[3]);
            float r00 = d0[0] - __bfloat162float(__float2bfloat16(d0[0]));
            float r01 = d0[1] - __bfloat162float(__float2bfloat16(d0[1]));
            float r02 = d0[2] - __bfloat162float(__float2bfloat16(d0[2]));
            float r03 = d0[3] - __bfloat162float(__float2bfloat16(d0[3]));
            float r10 = d1[0] - __bfloat162float(__float2bfloat16(d1[0]));
            float r11 = d1[1] - __bfloat162float(__float2bfloat16(d1[1]));
            float r12 = d1[2] - __bfloat162float(__float2bfloat16(d1[2]));
            float r13 = d1[3] - __bfloat162float(__float2bfloat16(d1[3]));
            bl2[ks][0] = packbf(r00, r01);
            bl2[ks][1] = packbf(r02, r03);
            bl2[ks][2] = packbf(r10, r11);
            bl2[ks][3] = packbf(r12, r13);
        }

        float a2[4][4];
        #pragma unroll
        for (int nt = 0; nt < 4; ++nt) {
            int c0 = nt * 8 + (l & 3) * 2;
            float blo = sM[32 + c0], bhi = sM[32 + c0 + 1];
            a2[nt][0] = blo; a2[nt][1] = bhi; a2[nt][2] = blo; a2[nt][3] = bhi;
        }
        #pragma unroll
        for (int ks = 0; ks < 2; ++ks)
            #pragma unroll
            for (int nt = 0; nt < 4; ++nt) {
                uint2 Bh = Mf[(((1 * 2 + 0) * 2 + ks) * 4 + nt) * 32 + l];
                uint2 Bl = Mf[(((1 * 2 + 1) * 2 + ks) * 4 + nt) * 32 + l];
                mma16816(a2[nt], bh2[ks][0], bh2[ks][1], bh2[ks][2], bh2[ks][3], Bh.x, Bh.y);
                mma16816(a2[nt], bh2[ks][0], bh2[ks][1], bh2[ks][2], bh2[ks][3], Bl.x, Bl.y);
                mma16816(a2[nt], bl2[ks][0], bl2[ks][1], bl2[ks][2], bl2[ks][3], Bh.x, Bh.y);
            }

        float s0 = 0.f, s1 = 0.f;
        #pragma unroll
        for (int nt = 0; nt < 4; ++nt) {
            int c0 = nt * 8 + (l & 3) * 2;
            float lw0 = sM[64 + c0], lw1 = sM[64 + c0 + 1];
            s0 = fmaf(fmaxf(a2[nt][0], 0.f), lw0, s0);
            s0 = fmaf(fmaxf(a2[nt][1], 0.f), lw1, s0);
            s1 = fmaf(fmaxf(a2[nt][2], 0.f), lw0, s1);
            s1 = fmaf(fmaxf(a2[nt][3], 0.f), lw1, s1);
        }
        s0 += __shfl_xor_sync(0xffffffff, s0, 1);
        s0 += __shfl_xor_sync(0xffffffff, s0, 2);
        s1 += __shfl_xor_sync(0xffffffff, s1, 1);
        s1 += __shfl_xor_sync(0xffffffff, s1, 2);
        if ((l & 3) == 0) {
            float lb = sM[96];
            out[b0 + slab * 16 + (l >> 2)]     = s0 + lb;
            out[b0 + slab * 16 + (l >> 2) + 8] = s1 + lb;
        }
    }
}

extern "C" void kernel_launch(void* const* d_in, const int* in_sizes, int n_in,
                              void* d_out, int out_size) {
    const int*   Xi     = (const int*)  d_in[0];
    const float* Xv     = (const float*)d_in[1];
    const float* tables = (const float*)d_in[2];
    const float* W1     = (const float*)d_in[3];
    const float* Wi     = (const float*)d_in[4];
    const float* lin1_w = (const float*)d_in[5];
    const float* lin1_b = (const float*)d_in[6];
    const float* lin2_w = (const float*)d_in[7];
    const float* lin2_b = (const float*)d_in[8];
    const float* last_w = (const float*)d_in[9];
    const float* last_b = (const float*)d_in[10];
    float* out = (float*)d_out;

    static bool attr_set = false;
    if (!attr_set) {
        cudaFuncSetAttribute(pnn_kernel, cudaFuncAttributeMaxDynamicSharedMemorySize, SMEM_BYTES);
        attr_set = true;
    }

    prep_all_kernel<<<(21504 + 255) / 256, 256>>>(W1, Wi, lin1_w, lin2_w);
    pnn_kernel<<<BATCH / ROWSPB, THREADS, SMEM_BYTES>>>(
        Xi, Xv, tables, lin1_b, lin2_b, last_w, last_b, out);
}